// round 13
// baseline (speedup 1.0000x reference)
#include <cuda_runtime.h>
#include <cuda_fp16.h>
#include <cstdint>

// Problem constants
#define BB   4
#define SS   2048
#define DD   1024
#define HH   16
#define DKK  64
#define MM   (BB*SS)          // 8192 rows
#define LDQKV (3*DD)          // fused qkv row stride
#define NX   (MM*DD)          // 1<<23
#define NW   (DD*DD)          // 1<<20

// -------- scratch (device globals: no allocation allowed) --------
__device__ __half g_xh  [NX];           // x in fp16
__device__ __half g_wqkv[3*NW];         // packed [Wq;Wk;Wv] fp16
__device__ __half g_woh [NW];           // Wo fp16
__device__ __half g_qkv [MM*3*DD];      // fused qkv output
__device__ __half g_ah  [MM*DD];        // attention output

// -------- helpers --------
__device__ __forceinline__ uint32_t s2u(const void* p) {
    return (uint32_t)__cvta_generic_to_shared(p);
}
__device__ __forceinline__ void mma16(float* c, const uint32_t* a, const uint32_t* b) {
    asm volatile(
        "mma.sync.aligned.m16n8k16.row.col.f32.f16.f16.f32 "
        "{%0,%1,%2,%3}, {%4,%5,%6,%7}, {%8,%9}, {%0,%1,%2,%3};"
        : "+f"(c[0]), "+f"(c[1]), "+f"(c[2]), "+f"(c[3])
        : "r"(a[0]), "r"(a[1]), "r"(a[2]), "r"(a[3]), "r"(b[0]), "r"(b[1]));
}
__device__ __forceinline__ void ldsm4(uint32_t* r, const void* p) {
    uint32_t a = s2u(p);
    asm volatile("ldmatrix.sync.aligned.m8n8.x4.shared.b16 {%0,%1,%2,%3}, [%4];"
                 : "=r"(r[0]), "=r"(r[1]), "=r"(r[2]), "=r"(r[3]) : "r"(a));
}
__device__ __forceinline__ void ldsm4t(uint32_t* r, const void* p) {
    uint32_t a = s2u(p);
    asm volatile("ldmatrix.sync.aligned.m8n8.x4.trans.shared.b16 {%0,%1,%2,%3}, [%4];"
                 : "=r"(r[0]), "=r"(r[1]), "=r"(r[2]), "=r"(r[3]) : "r"(a));
}
__device__ __forceinline__ void cp16(void* s, const void* g) {
    uint32_t sa = s2u(s);
    asm volatile("cp.async.cg.shared.global [%0], [%1], 16;" :: "r"(sa), "l"(g));
}
__device__ __forceinline__ uint32_t packh2(float a, float b) {
    __half2 h = __floats2half2_rn(a, b);
    return *(uint32_t*)&h;
}

// ============================================================================
// Fused fp32 -> fp16 conversion of ALL inputs in one launch.
// ============================================================================
__global__ void __launch_bounds__(256) convert_all(
    const float* __restrict__ x,  const float* __restrict__ Wq,
    const float* __restrict__ Wk, const float* __restrict__ Wv,
    const float* __restrict__ Wo,
    __half* __restrict__ xh, __half* __restrict__ wqkv, __half* __restrict__ woh)
{
    int i = (blockIdx.x * blockDim.x + threadIdx.x) << 3;
    const float* src;
    __half* dst;
    int o;
    if (i < NX) {
        src = x; dst = xh; o = i;
    } else {
        int j = i - NX;
        int w = j >> 20;              // which weight (NW = 1<<20)
        o = j & (NW - 1);
        src = (w == 0) ? Wq : (w == 1) ? Wk : (w == 2) ? Wv : Wo;
        dst = (w < 3) ? wqkv + ((size_t)w << 20) : woh;
    }
    float4 v0 = *(const float4*)&src[o];
    float4 v1 = *(const float4*)&src[o + 4];
    uint4 r;
    r.x = packh2(v0.x, v0.y); r.y = packh2(v0.z, v0.w);
    r.z = packh2(v1.x, v1.y); r.w = packh2(v1.z, v1.w);
    *(uint4*)&dst[o] = r;
}

// ============================================================================
// FP16 GEMM: C[M,N] = A[M,K] * B[N,K]^T  (fp32 accum, HMMA)
// CTA tile 128x128, K-tile 64, 3-stage cp.async pipeline, 256 threads
// (8 warps 2x4, warp tile 64x32). 2 CTAs/SM. (At legacy-HMMA ceiling; frozen.)
// ============================================================================
#define GSTR  72                         // smem row stride in halves (144B)
#define AB_ST (128*GSTR)                 // halves per matrix per stage
#define ST_H  (2*AB_ST)
#define NSTG  3
#define GEMM_SMEM (NSTG * ST_H * 2)      // 110592 B -> 2 CTAs/SM

__device__ __forceinline__ void g_stage_load(__half* stg,
    const __half* Ag, const __half* Bg, int K, int kk, int tid)
{
    __half* As = stg;
    __half* Bs = stg + AB_ST;
    #pragma unroll
    for (int i = 0; i < 4; i++) {          // A: 128 rows x 8 chunks
        int idx = tid + (i << 8);
        int r = idx >> 3, c = (idx & 7) << 3;
        cp16(As + r * GSTR + c, Ag + (size_t)r * K + kk + c);
    }
    #pragma unroll
    for (int i = 0; i < 4; i++) {          // B: 128 rows x 8 chunks
        int idx = tid + (i << 8);
        int r = idx >> 3, c = (idx & 7) << 3;
        cp16(Bs + r * GSTR + c, Bg + (size_t)r * K + kk + c);
    }
}

template<bool HALF_OUT>
__global__ void __launch_bounds__(256, 2) gemm_f16(
    const __half* __restrict__ A, const __half* __restrict__ Bw,
    void* __restrict__ Cout, int K, int ldc)
{
    extern __shared__ __half smh[];

    const int tid  = threadIdx.x;
    const int warp = tid >> 5, lane = tid & 31;
    const int wm = (warp >> 2) * 64;      // 0 / 64
    const int wn = (warp & 3) * 32;       // 0..96
    const int g  = lane >> 2, tg = lane & 3;
    const int bn = blockIdx.x * 128, bm = blockIdx.y * 128;

    const int arow = (lane & 7) + ((lane & 8) ? 8 : 0);
    const int acol = (lane & 16) ? 8 : 0;
    const int brow = (lane & 7) + ((lane & 16) ? 8 : 0);
    const int bcol = (lane & 8) ? 8 : 0;

    const __half* Ag = A  + (size_t)bm * K;
    const __half* Bg = Bw + (size_t)bn * K;

    float acc[4][4][4];
    #pragma unroll
    for (int mi = 0; mi < 4; mi++)
        #pragma unroll
        for (int ni = 0; ni < 4; ni++)
            #pragma unroll
            for (int r = 0; r < 4; r++) acc[mi][ni][r] = 0.f;

    const int KT = K >> 6;

    // prologue: stage 0 and 1
    g_stage_load(smh,        Ag, Bg, K, 0,  tid);
    asm volatile("cp.async.commit_group;");
    g_stage_load(smh + ST_H, Ag, Bg, K, 64, tid);
    asm volatile("cp.async.commit_group;");

    int st = 0;
    for (int kt = 0; kt < KT; kt++) {
        if (kt + 1 < KT) asm volatile("cp.async.wait_group 1;");
        else             asm volatile("cp.async.wait_group 0;");
        __syncthreads();

        if (kt + 2 < KT) {
            int ns = st + 2; if (ns >= NSTG) ns -= NSTG;
            g_stage_load(smh + ns * ST_H, Ag, Bg, K, (kt + 2) << 6, tid);
            asm volatile("cp.async.commit_group;");
        }

        const __half* as = smh + st * ST_H;
        const __half* bs = as + AB_ST;

        #pragma unroll
        for (int ks = 0; ks < 4; ks++) {
            const int kk = ks << 4;
            uint32_t af[4][4], bf[2][4];
            #pragma unroll
            for (int mi = 0; mi < 4; mi++)
                ldsm4(af[mi], &as[(wm + mi * 16 + arow) * GSTR + kk + acol]);
            #pragma unroll
            for (int nj = 0; nj < 2; nj++)
                ldsm4(bf[nj], &bs[(wn + nj * 16 + brow) * GSTR + kk + bcol]);
            #pragma unroll
            for (int mi = 0; mi < 4; mi++)
                #pragma unroll
                for (int nj = 0; nj < 2; nj++) {
                    mma16(acc[mi][nj * 2],     af[mi], bf[nj]);
                    mma16(acc[mi][nj * 2 + 1], af[mi], bf[nj] + 2);
                }
        }

        if (++st >= NSTG) st = 0;
    }

    // epilogue
    #pragma unroll
    for (int mi = 0; mi < 4; mi++) {
        int row = bm + wm + mi * 16 + g;
        #pragma unroll
        for (int ni = 0; ni < 4; ni++) {
            int col = bn + wn + ni * 8 + (tg << 1);
            if (HALF_OUT) {
                __half* C = (__half*)Cout;
                *(__half2*)&C[(size_t)row * ldc + col] =
                    __floats2half2_rn(acc[mi][ni][0], acc[mi][ni][1]);
                *(__half2*)&C[(size_t)(row + 8) * ldc + col] =
                    __floats2half2_rn(acc[mi][ni][2], acc[mi][ni][3]);
            } else {
                float* C = (float*)Cout;
                *(float2*)&C[(size_t)row * ldc + col] =
                    make_float2(acc[mi][ni][0], acc[mi][ni][1]);
                *(float2*)&C[(size_t)(row + 8) * ldc + col] =
                    make_float2(acc[mi][ni][2], acc[mi][ni][3]);
            }
        }
    }
}

// ============================================================================
// Causal flash attention. Softmax in log2 domain: scores pre-scaled by
// sscale*log2e; p = exp2(s' - m') via h2exp2 on f16x2 (half the MUFU ops),
// ex2 output doubles as the packed PV A-fragment. l accumulates in fp32.
// qtile order reversed so longest blocks launch first.
// ============================================================================
#define QS2 72   // smem row stride in halves

__global__ void __launch_bounds__(256) attn_kernel(
    const __half* __restrict__ Q, const __half* __restrict__ Kb,
    const __half* __restrict__ Vb, __half* __restrict__ O)
{
    extern __shared__ __half sm[];
    __half* Qs = sm;                       // 128 x QS2
    __half* Ks = Qs + 128 * QS2;           // [2][64][QS2]
    __half* Vs = Ks + 2 * 64 * QS2;        // [2][64][QS2]

    const int tid  = threadIdx.x;
    const int warp = tid >> 5, lane = tid & 31;
    const int g = lane >> 2, tg = lane & 3;
    const int qtile = (gridDim.x - 1) - blockIdx.x;   // longest first
    const int h = blockIdx.y, b = blockIdx.z;
    const int qbase = qtile * 128;
    const int hoff  = h * DKK;

    const int arow = (lane & 7) + ((lane & 8) ? 8 : 0);
    const int acol = (lane & 16) ? 8 : 0;
    const int brow = (lane & 7) + ((lane & 16) ? 8 : 0);
    const int bcol = (lane & 8) ? 8 : 0;
    const int vrow = (lane & 7) + ((lane & 8) ? 8 : 0);
    const int vcol = (lane & 16) ? 8 : 0;

    #pragma unroll
    for (int i = 0; i < 4; i++) {
        int idx = tid + (i << 8);
        int r = idx >> 3, c = (idx & 7) << 3;
        cp16(Qs + r * QS2 + c, Q + (size_t)(b * SS + qbase + r) * LDQKV + hoff + c);
    }
    #pragma unroll
    for (int i = 0; i < 4; i++) {
        int idx = tid + (i << 8);
        int mat = idx >> 9, r = (idx >> 3) & 63, c = (idx & 7) << 3;
        const __half* src = Kb;
        __half* dst = Ks;
        if (mat) { src = Vb; dst = Vs; }
        cp16(dst + r * QS2 + c, src + (size_t)(b * SS + r) * LDQKV + hoff + c);
    }
    asm volatile("cp.async.commit_group;");
    asm volatile("cp.async.wait_group 0;");
    __syncthreads();

    uint32_t qf[4][4];
    #pragma unroll
    for (int ks = 0; ks < 4; ks++)
        ldsm4(qf[ks], &Qs[(warp * 16 + arow) * QS2 + (ks << 4) + acol]);

    float m0 = -1e30f, m1 = -1e30f, l0 = 0.f, l1 = 0.f;
    float o[8][4];
    #pragma unroll
    for (int ni = 0; ni < 8; ni++)
        #pragma unroll
        for (int r = 0; r < 4; r++) o[ni][r] = 0.f;

    const int pr0 = warp * 16 + g;
    const int r0g = qbase + pr0;
    const int r1g = r0g + 8;
    const float qscale = 0.125f * 1.44269504089f;  // 1/sqrt(64) * log2(e)
    const int jmax = (qbase + 127) >> 6;

    for (int j = 0; j <= jmax; j++) {
        const int kvbase = j << 6;
        const int cur = j & 1;

        if (j + 1 <= jmax) {
            const int nb = (j + 1) & 1;
            const int nkv = (j + 1) << 6;
            #pragma unroll
            for (int i = 0; i < 4; i++) {
                int idx = tid + (i << 8);
                int mat = idx >> 9, r = (idx >> 3) & 63, c = (idx & 7) << 3;
                const __half* src = Kb;
                __half* dst = Ks + nb * 64 * QS2;
                if (mat) { src = Vb; dst = Vs + nb * 64 * QS2; }
                cp16(dst + r * QS2 + c, src + (size_t)(b * SS + nkv + r) * LDQKV + hoff + c);
            }
            asm volatile("cp.async.commit_group;");
        }

        if (kvbase <= qbase + warp * 16 + 15) {
            const __half* ks_ = Ks + cur * 64 * QS2;
            const __half* vs_ = Vs + cur * 64 * QS2;

            float sc[8][4];
            #pragma unroll
            for (int ni = 0; ni < 8; ni++)
                #pragma unroll
                for (int r = 0; r < 4; r++) sc[ni][r] = 0.f;

            #pragma unroll
            for (int ks = 0; ks < 4; ks++) {
                const int kk = ks << 4;
                #pragma unroll
                for (int nj = 0; nj < 4; nj++) {
                    uint32_t kf[4];
                    ldsm4(kf, &ks_[(nj * 16 + brow) * QS2 + kk + bcol]);
                    mma16(sc[nj * 2],     qf[ks], kf);
                    mma16(sc[nj * 2 + 1], qf[ks], kf + 2);
                }
            }

            // ---- scale into log2 domain + causal mask ----
            const bool need_mask = (kvbase + 63 > qbase + warp * 16);
            if (need_mask) {
                #pragma unroll
                for (int ni = 0; ni < 8; ni++) {
                    int c0 = kvbase + ni * 8 + (tg << 1), c1 = c0 + 1;
                    sc[ni][0] = (c0 <= r0g) ? sc[ni][0] * qscale : -1e30f;
                    sc[ni][1] = (c1 <= r0g) ? sc[ni][1] * qscale : -1e30f;
                    sc[ni][2] = (c0 <= r1g) ? sc[ni][2] * qscale : -1e30f;
                    sc[ni][3] = (c1 <= r1g) ? sc[ni][3] * qscale : -1e30f;
                }
            } else {
                #pragma unroll
                for (int ni = 0; ni < 8; ni++)
                    #pragma unroll
                    for (int r = 0; r < 4; r++) sc[ni][r] *= qscale;
            }

            // ---- online softmax (log2 domain, quad shuffles) ----
            float t0 = -1e30f, t1 = -1e30f;
            #pragma unroll
            for (int ni = 0; ni < 8; ni++) {
                t0 = fmaxf(t0, fmaxf(sc[ni][0], sc[ni][1]));
                t1 = fmaxf(t1, fmaxf(sc[ni][2], sc[ni][3]));
            }
            t0 = fmaxf(t0, __shfl_xor_sync(0xffffffffu, t0, 1));
            t0 = fmaxf(t0, __shfl_xor_sync(0xffffffffu, t0, 2));
            t1 = fmaxf(t1, __shfl_xor_sync(0xffffffffu, t1, 1));
            t1 = fmaxf(t1, __shfl_xor_sync(0xffffffffu, t1, 2));

            float nm0 = fmaxf(m0, t0), nm1 = fmaxf(m1, t1);
            float cor0 = exp2f(m0 - nm0), cor1 = exp2f(m1 - nm1);

            // p = exp2(s' - m') on packed halves; pe IS the PV A-fragment
            uint32_t pe[8][2];
            float s0 = 0.f, s1 = 0.f;
            #pragma unroll
            for (int ni = 0; ni < 8; ni++) {
                __half2 h0 = __floats2half2_rn(sc[ni][0] - nm0, sc[ni][1] - nm0);
                __half2 h1 = __floats2half2_rn(sc[ni][2] - nm1, sc[ni][3] - nm1);
                __half2 e0 = h2exp2(h0);
                __half2 e1 = h2exp2(h1);
                pe[ni][0] = *(uint32_t*)&e0;
                pe[ni][1] = *(uint32_t*)&e1;
                float2 f0 = __half22float2(e0);
                float2 f1 = __half22float2(e1);
                s0 += f0.x + f0.y;
                s1 += f1.x + f1.y;
            }
            s0 += __shfl_xor_sync(0xffffffffu, s0, 1);
            s0 += __shfl_xor_sync(0xffffffffu, s0, 2);
            s1 += __shfl_xor_sync(0xffffffffu, s1, 1);
            s1 += __shfl_xor_sync(0xffffffffu, s1, 2);

            l0 = l0 * cor0 + s0;
            l1 = l1 * cor1 + s1;
            m0 = nm0; m1 = nm1;

            #pragma unroll
            for (int ni = 0; ni < 8; ni++) {
                o[ni][0] *= cor0; o[ni][1] *= cor0;
                o[ni][2] *= cor1; o[ni][3] *= cor1;
            }

            // ---- O += P V ----
            #pragma unroll
            for (int ks = 0; ks < 4; ks++) {
                uint32_t pa[4];
                pa[0] = pe[2 * ks][0];
                pa[1] = pe[2 * ks][1];
                pa[2] = pe[2 * ks + 1][0];
                pa[3] = pe[2 * ks + 1][1];
                #pragma unroll
                for (int nj = 0; nj < 4; nj++) {
                    uint32_t vf[4];
                    ldsm4t(vf, &vs_[((ks << 4) + vrow) * QS2 + nj * 16 + vcol]);
                    mma16(o[nj * 2],     pa, vf);
                    mma16(o[nj * 2 + 1], pa, vf + 2);
                }
            }
        }

        if (j + 1 <= jmax) {
            asm volatile("cp.async.wait_group 0;");
            __syncthreads();
        }
    }

    float inv0 = 1.f / l0, inv1 = 1.f / l1;
    size_t orow = (size_t)(b * SS + qbase + pr0) * DD + hoff;
    #pragma unroll
    for (int ni = 0; ni < 8; ni++) {
        int pc = ni * 8 + (tg << 1);
        *(__half2*)&O[orow + pc] =
            __floats2half2_rn(o[ni][0] * inv0, o[ni][1] * inv0);
        *(__half2*)&O[orow + 8 * DD + pc] =
            __floats2half2_rn(o[ni][2] * inv1, o[ni][3] * inv1);
    }
}

// ============================================================================
// launcher
// ============================================================================
#define ATTN_SMEM ((128 + 2 * 64 + 2 * 64) * QS2 * 2)          // 55296 B

extern "C" void kernel_launch(void* const* d_in, const int* in_sizes, int n_in,
                              void* d_out, int out_size)
{
    const float* x  = (const float*)d_in[0];
    const float* Wq = (const float*)d_in[1];
    const float* Wk = (const float*)d_in[2];
    const float* Wv = (const float*)d_in[3];
    const float* Wo = (const float*)d_in[4];
    float* out = (float*)d_out;

    __half *xh, *wqkv, *woh, *qkv, *ah;
    cudaGetSymbolAddress((void**)&xh,   g_xh);
    cudaGetSymbolAddress((void**)&wqkv, g_wqkv);
    cudaGetSymbolAddress((void**)&woh,  g_woh);
    cudaGetSymbolAddress((void**)&qkv,  g_qkv);
    cudaGetSymbolAddress((void**)&ah,   g_ah);

    cudaFuncSetAttribute(gemm_f16<true>,  cudaFuncAttributeMaxDynamicSharedMemorySize, GEMM_SMEM);
    cudaFuncSetAttribute(gemm_f16<false>, cudaFuncAttributeMaxDynamicSharedMemorySize, GEMM_SMEM);
    cudaFuncSetAttribute(attn_kernel,     cudaFuncAttributeMaxDynamicSharedMemorySize, ATTN_SMEM);

    // ONE conversion launch: x + Wq/Wk/Wv (packed) + Wo
    const int NTOT = NX + 4 * NW;                  // 12582912
    convert_all<<<NTOT / 8 / 256, 256>>>(x, Wq, Wk, Wv, Wo, xh, wqkv, woh);

    // fused QKV projection: [8192,1024] x [3072,1024]^T -> [8192,3072] fp16
    dim3 gq(LDQKV / 128, MM / 128);   // (24, 64)
    gemm_f16<true><<<gq, 256, GEMM_SMEM>>>(xh, wqkv, qkv, DD, LDQKV);

    // attention (reads qkv with stride 3072)
    dim3 ga(SS / 128, HH, BB);        // (16, 16, 4)
    attn_kernel<<<ga, 256, ATTN_SMEM>>>(qkv, qkv + DD, qkv + 2 * DD, ah);

    // output projection: [8192,1024] x [1024,1024]^T -> fp32 out
    dim3 go(DD / 128, MM / 128);      // (8, 64)
    gemm_f16<false><<<go, 256, GEMM_SMEM>>>(ah, woh, out, DD, DD);
}

// round 14
// speedup vs baseline: 1.5288x; 1.5288x over previous
#include <cuda_runtime.h>
#include <cuda_fp16.h>
#include <cstdint>

// Problem constants
#define BB   4
#define SS   2048
#define DD   1024
#define HH   16
#define DKK  64
#define MM   (BB*SS)          // 8192 rows
#define LDQKV (3*DD)          // fused qkv row stride
#define NX   (MM*DD)          // 1<<23
#define NW   (DD*DD)          // 1<<20

// -------- scratch (device globals: no allocation allowed) --------
__device__ __half g_xh  [NX];           // x in fp16
__device__ __half g_wqkv[3*NW];         // packed [Wq;Wk;Wv] fp16
__device__ __half g_woh [NW];           // Wo fp16
__device__ __half g_qkv [MM*3*DD];      // fused qkv output
__device__ __half g_ah  [MM*DD];        // attention output

// -------- helpers --------
__device__ __forceinline__ uint32_t s2u(const void* p) {
    return (uint32_t)__cvta_generic_to_shared(p);
}
__device__ __forceinline__ void mma16(float* c, const uint32_t* a, const uint32_t* b) {
    asm volatile(
        "mma.sync.aligned.m16n8k16.row.col.f32.f16.f16.f32 "
        "{%0,%1,%2,%3}, {%4,%5,%6,%7}, {%8,%9}, {%0,%1,%2,%3};"
        : "+f"(c[0]), "+f"(c[1]), "+f"(c[2]), "+f"(c[3])
        : "r"(a[0]), "r"(a[1]), "r"(a[2]), "r"(a[3]), "r"(b[0]), "r"(b[1]));
}
__device__ __forceinline__ void ldsm4(uint32_t* r, const void* p) {
    uint32_t a = s2u(p);
    asm volatile("ldmatrix.sync.aligned.m8n8.x4.shared.b16 {%0,%1,%2,%3}, [%4];"
                 : "=r"(r[0]), "=r"(r[1]), "=r"(r[2]), "=r"(r[3]) : "r"(a));
}
__device__ __forceinline__ void ldsm4t(uint32_t* r, const void* p) {
    uint32_t a = s2u(p);
    asm volatile("ldmatrix.sync.aligned.m8n8.x4.trans.shared.b16 {%0,%1,%2,%3}, [%4];"
                 : "=r"(r[0]), "=r"(r[1]), "=r"(r[2]), "=r"(r[3]) : "r"(a));
}
__device__ __forceinline__ void cp16(void* s, const void* g) {
    uint32_t sa = s2u(s);
    asm volatile("cp.async.cg.shared.global [%0], [%1], 16;" :: "r"(sa), "l"(g));
}
__device__ __forceinline__ uint32_t packh2(float a, float b) {
    __half2 h = __floats2half2_rn(a, b);
    return *(uint32_t*)&h;
}

// ============================================================================
// Fused fp32 -> fp16 conversion of ALL inputs in one launch.
// ============================================================================
__global__ void __launch_bounds__(256) convert_all(
    const float* __restrict__ x,  const float* __restrict__ Wq,
    const float* __restrict__ Wk, const float* __restrict__ Wv,
    const float* __restrict__ Wo,
    __half* __restrict__ xh, __half* __restrict__ wqkv, __half* __restrict__ woh)
{
    int i = (blockIdx.x * blockDim.x + threadIdx.x) << 3;
    const float* src;
    __half* dst;
    int o;
    if (i < NX) {
        src = x; dst = xh; o = i;
    } else {
        int j = i - NX;
        int w = j >> 20;              // which weight (NW = 1<<20)
        o = j & (NW - 1);
        src = (w == 0) ? Wq : (w == 1) ? Wk : (w == 2) ? Wv : Wo;
        dst = (w < 3) ? wqkv + ((size_t)w << 20) : woh;
    }
    float4 v0 = *(const float4*)&src[o];
    float4 v1 = *(const float4*)&src[o + 4];
    uint4 r;
    r.x = packh2(v0.x, v0.y); r.y = packh2(v0.z, v0.w);
    r.z = packh2(v1.x, v1.y); r.w = packh2(v1.z, v1.w);
    *(uint4*)&dst[o] = r;
}

// ============================================================================
// FP16 GEMM: C[M,N] = A[M,K] * B[N,K]^T  (fp32 accum, HMMA)
// CTA tile 128x128, K-tile 64, 3-stage cp.async pipeline, 256 threads
// (8 warps 2x4, warp tile 64x32). 2 CTAs/SM. (At legacy-HMMA ceiling; frozen.)
// ============================================================================
#define GSTR  72                         // smem row stride in halves (144B)
#define AB_ST (128*GSTR)                 // halves per matrix per stage
#define ST_H  (2*AB_ST)
#define NSTG  3
#define GEMM_SMEM (NSTG * ST_H * 2)      // 110592 B -> 2 CTAs/SM

__device__ __forceinline__ void g_stage_load(__half* stg,
    const __half* Ag, const __half* Bg, int K, int kk, int tid)
{
    __half* As = stg;
    __half* Bs = stg + AB_ST;
    #pragma unroll
    for (int i = 0; i < 4; i++) {          // A: 128 rows x 8 chunks
        int idx = tid + (i << 8);
        int r = idx >> 3, c = (idx & 7) << 3;
        cp16(As + r * GSTR + c, Ag + (size_t)r * K + kk + c);
    }
    #pragma unroll
    for (int i = 0; i < 4; i++) {          // B: 128 rows x 8 chunks
        int idx = tid + (i << 8);
        int r = idx >> 3, c = (idx & 7) << 3;
        cp16(Bs + r * GSTR + c, Bg + (size_t)r * K + kk + c);
    }
}

template<bool HALF_OUT>
__global__ void __launch_bounds__(256, 2) gemm_f16(
    const __half* __restrict__ A, const __half* __restrict__ Bw,
    void* __restrict__ Cout, int K, int ldc)
{
    extern __shared__ __half smh[];

    const int tid  = threadIdx.x;
    const int warp = tid >> 5, lane = tid & 31;
    const int wm = (warp >> 2) * 64;      // 0 / 64
    const int wn = (warp & 3) * 32;       // 0..96
    const int g  = lane >> 2, tg = lane & 3;
    const int bn = blockIdx.x * 128, bm = blockIdx.y * 128;

    const int arow = (lane & 7) + ((lane & 8) ? 8 : 0);
    const int acol = (lane & 16) ? 8 : 0;
    const int brow = (lane & 7) + ((lane & 16) ? 8 : 0);
    const int bcol = (lane & 8) ? 8 : 0;

    const __half* Ag = A  + (size_t)bm * K;
    const __half* Bg = Bw + (size_t)bn * K;

    float acc[4][4][4];
    #pragma unroll
    for (int mi = 0; mi < 4; mi++)
        #pragma unroll
        for (int ni = 0; ni < 4; ni++)
            #pragma unroll
            for (int r = 0; r < 4; r++) acc[mi][ni][r] = 0.f;

    const int KT = K >> 6;

    // prologue: stage 0 and 1
    g_stage_load(smh,        Ag, Bg, K, 0,  tid);
    asm volatile("cp.async.commit_group;");
    g_stage_load(smh + ST_H, Ag, Bg, K, 64, tid);
    asm volatile("cp.async.commit_group;");

    int st = 0;
    for (int kt = 0; kt < KT; kt++) {
        if (kt + 1 < KT) asm volatile("cp.async.wait_group 1;");
        else             asm volatile("cp.async.wait_group 0;");
        __syncthreads();

        if (kt + 2 < KT) {
            int ns = st + 2; if (ns >= NSTG) ns -= NSTG;
            g_stage_load(smh + ns * ST_H, Ag, Bg, K, (kt + 2) << 6, tid);
            asm volatile("cp.async.commit_group;");
        }

        const __half* as = smh + st * ST_H;
        const __half* bs = as + AB_ST;

        #pragma unroll
        for (int ks = 0; ks < 4; ks++) {
            const int kk = ks << 4;
            uint32_t af[4][4], bf[2][4];
            #pragma unroll
            for (int mi = 0; mi < 4; mi++)
                ldsm4(af[mi], &as[(wm + mi * 16 + arow) * GSTR + kk + acol]);
            #pragma unroll
            for (int nj = 0; nj < 2; nj++)
                ldsm4(bf[nj], &bs[(wn + nj * 16 + brow) * GSTR + kk + bcol]);
            #pragma unroll
            for (int mi = 0; mi < 4; mi++)
                #pragma unroll
                for (int nj = 0; nj < 2; nj++) {
                    mma16(acc[mi][nj * 2],     af[mi], bf[nj]);
                    mma16(acc[mi][nj * 2 + 1], af[mi], bf[nj] + 2);
                }
        }

        if (++st >= NSTG) st = 0;
    }

    // epilogue
    #pragma unroll
    for (int mi = 0; mi < 4; mi++) {
        int row = bm + wm + mi * 16 + g;
        #pragma unroll
        for (int ni = 0; ni < 4; ni++) {
            int col = bn + wn + ni * 8 + (tg << 1);
            if (HALF_OUT) {
                __half* C = (__half*)Cout;
                *(__half2*)&C[(size_t)row * ldc + col] =
                    __floats2half2_rn(acc[mi][ni][0], acc[mi][ni][1]);
                *(__half2*)&C[(size_t)(row + 8) * ldc + col] =
                    __floats2half2_rn(acc[mi][ni][2], acc[mi][ni][3]);
            } else {
                float* C = (float*)Cout;
                *(float2*)&C[(size_t)row * ldc + col] =
                    make_float2(acc[mi][ni][0], acc[mi][ni][1]);
                *(float2*)&C[(size_t)(row + 8) * ldc + col] =
                    make_float2(acc[mi][ni][2], acc[mi][ni][3]);
            }
        }
    }
}

// ============================================================================
// Causal flash attention. Softmax in log2 domain: scores pre-scaled by
// sscale*log2e; p = exp2(s' - m') via h2exp2 on f16x2, ex2 output doubles as
// the packed PV A-fragment. l accumulates in fp32.
// ============================================================================
#define QS2 72   // smem row stride in halves

__global__ void __launch_bounds__(256) attn_kernel(
    const __half* __restrict__ Q, const __half* __restrict__ Kb,
    const __half* __restrict__ Vb, __half* __restrict__ O)
{
    extern __shared__ __half sm[];
    __half* Qs = sm;                       // 128 x QS2
    __half* Ks = Qs + 128 * QS2;           // [2][64][QS2]
    __half* Vs = Ks + 2 * 64 * QS2;        // [2][64][QS2]

    const int tid  = threadIdx.x;
    const int warp = tid >> 5, lane = tid & 31;
    const int g = lane >> 2, tg = lane & 3;
    const int qtile = (gridDim.x - 1) - blockIdx.x;   // longest first
    const int h = blockIdx.y, b = blockIdx.z;
    const int qbase = qtile * 128;
    const int hoff  = h * DKK;

    const int arow = (lane & 7) + ((lane & 8) ? 8 : 0);
    const int acol = (lane & 16) ? 8 : 0;
    const int brow = (lane & 7) + ((lane & 16) ? 8 : 0);
    const int bcol = (lane & 8) ? 8 : 0;
    const int vrow = (lane & 7) + ((lane & 8) ? 8 : 0);
    const int vcol = (lane & 16) ? 8 : 0;

    #pragma unroll
    for (int i = 0; i < 4; i++) {
        int idx = tid + (i << 8);
        int r = idx >> 3, c = (idx & 7) << 3;
        cp16(Qs + r * QS2 + c, Q + (size_t)(b * SS + qbase + r) * LDQKV + hoff + c);
    }
    #pragma unroll
    for (int i = 0; i < 4; i++) {
        int idx = tid + (i << 8);
        int mat = idx >> 9, r = (idx >> 3) & 63, c = (idx & 7) << 3;
        const __half* src = Kb;
        __half* dst = Ks;
        if (mat) { src = Vb; dst = Vs; }
        cp16(dst + r * QS2 + c, src + (size_t)(b * SS + r) * LDQKV + hoff + c);
    }
    asm volatile("cp.async.commit_group;");
    asm volatile("cp.async.wait_group 0;");
    __syncthreads();

    uint32_t qf[4][4];
    #pragma unroll
    for (int ks = 0; ks < 4; ks++)
        ldsm4(qf[ks], &Qs[(warp * 16 + arow) * QS2 + (ks << 4) + acol]);

    float m0 = -1e30f, m1 = -1e30f, l0 = 0.f, l1 = 0.f;
    float o[8][4];
    #pragma unroll
    for (int ni = 0; ni < 8; ni++)
        #pragma unroll
        for (int r = 0; r < 4; r++) o[ni][r] = 0.f;

    const int pr0 = warp * 16 + g;
    const int r0g = qbase + pr0;
    const int r1g = r0g + 8;
    const float qscale = 0.125f * 1.44269504089f;  // 1/sqrt(64) * log2(e)
    const int jmax = (qbase + 127) >> 6;

    for (int j = 0; j <= jmax; j++) {
        const int kvbase = j << 6;
        const int cur = j & 1;

        if (j + 1 <= jmax) {
            const int nb = (j + 1) & 1;
            const int nkv = (j + 1) << 6;
            #pragma unroll
            for (int i = 0; i < 4; i++) {
                int idx = tid + (i << 8);
                int mat = idx >> 9, r = (idx >> 3) & 63, c = (idx & 7) << 3;
                const __half* src = Kb;
                __half* dst = Ks + nb * 64 * QS2;
                if (mat) { src = Vb; dst = Vs + nb * 64 * QS2; }
                cp16(dst + r * QS2 + c, src + (size_t)(b * SS + nkv + r) * LDQKV + hoff + c);
            }
            asm volatile("cp.async.commit_group;");
        }

        if (kvbase <= qbase + warp * 16 + 15) {
            const __half* ks_ = Ks + cur * 64 * QS2;
            const __half* vs_ = Vs + cur * 64 * QS2;

            float sc[8][4];
            #pragma unroll
            for (int ni = 0; ni < 8; ni++)
                #pragma unroll
                for (int r = 0; r < 4; r++) sc[ni][r] = 0.f;

            #pragma unroll
            for (int ks = 0; ks < 4; ks++) {
                const int kk = ks << 4;
                #pragma unroll
                for (int nj = 0; nj < 4; nj++) {
                    uint32_t kf[4];
                    ldsm4(kf, &ks_[(nj * 16 + brow) * QS2 + kk + bcol]);
                    mma16(sc[nj * 2],     qf[ks], kf);
                    mma16(sc[nj * 2 + 1], qf[ks], kf + 2);
                }
            }

            // ---- scale into log2 domain + causal mask ----
            const bool need_mask = (kvbase + 63 > qbase + warp * 16);
            if (need_mask) {
                #pragma unroll
                for (int ni = 0; ni < 8; ni++) {
                    int c0 = kvbase + ni * 8 + (tg << 1), c1 = c0 + 1;
                    sc[ni][0] = (c0 <= r0g) ? sc[ni][0] * qscale : -1e30f;
                    sc[ni][1] = (c1 <= r0g) ? sc[ni][1] * qscale : -1e30f;
                    sc[ni][2] = (c0 <= r1g) ? sc[ni][2] * qscale : -1e30f;
                    sc[ni][3] = (c1 <= r1g) ? sc[ni][3] * qscale : -1e30f;
                }
            } else {
                #pragma unroll
                for (int ni = 0; ni < 8; ni++)
                    #pragma unroll
                    for (int r = 0; r < 4; r++) sc[ni][r] *= qscale;
            }

            // ---- online softmax (log2 domain, quad shuffles) ----
            float t0 = -1e30f, t1 = -1e30f;
            #pragma unroll
            for (int ni = 0; ni < 8; ni++) {
                t0 = fmaxf(t0, fmaxf(sc[ni][0], sc[ni][1]));
                t1 = fmaxf(t1, fmaxf(sc[ni][2], sc[ni][3]));
            }
            t0 = fmaxf(t0, __shfl_xor_sync(0xffffffffu, t0, 1));
            t0 = fmaxf(t0, __shfl_xor_sync(0xffffffffu, t0, 2));
            t1 = fmaxf(t1, __shfl_xor_sync(0xffffffffu, t1, 1));
            t1 = fmaxf(t1, __shfl_xor_sync(0xffffffffu, t1, 2));

            float nm0 = fmaxf(m0, t0), nm1 = fmaxf(m1, t1);
            float cor0 = exp2f(m0 - nm0), cor1 = exp2f(m1 - nm1);

            // p = exp2(s' - m') on packed halves; pe IS the PV A-fragment
            uint32_t pe[8][2];
            float s0 = 0.f, s1 = 0.f;
            #pragma unroll
            for (int ni = 0; ni < 8; ni++) {
                __half2 h0 = __floats2half2_rn(sc[ni][0] - nm0, sc[ni][1] - nm0);
                __half2 h1 = __floats2half2_rn(sc[ni][2] - nm1, sc[ni][3] - nm1);
                __half2 e0 = h2exp2(h0);
                __half2 e1 = h2exp2(h1);
                pe[ni][0] = *(uint32_t*)&e0;
                pe[ni][1] = *(uint32_t*)&e1;
                float2 f0 = __half22float2(e0);
                float2 f1 = __half22float2(e1);
                s0 += f0.x + f0.y;
                s1 += f1.x + f1.y;
            }
            s0 += __shfl_xor_sync(0xffffffffu, s0, 1);
            s0 += __shfl_xor_sync(0xffffffffu, s0, 2);
            s1 += __shfl_xor_sync(0xffffffffu, s1, 1);
            s1 += __shfl_xor_sync(0xffffffffu, s1, 2);

            l0 = l0 * cor0 + s0;
            l1 = l1 * cor1 + s1;
            m0 = nm0; m1 = nm1;

            #pragma unroll
            for (int ni = 0; ni < 8; ni++) {
                o[ni][0] *= cor0; o[ni][1] *= cor0;
                o[ni][2] *= cor1; o[ni][3] *= cor1;
            }

            // ---- O += P V ----
            #pragma unroll
            for (int ks = 0; ks < 4; ks++) {
                uint32_t pa[4];
                pa[0] = pe[2 * ks][0];
                pa[1] = pe[2 * ks][1];
                pa[2] = pe[2 * ks + 1][0];
                pa[3] = pe[2 * ks + 1][1];
                #pragma unroll
                for (int nj = 0; nj < 4; nj++) {
                    uint32_t vf[4];
                    ldsm4t(vf, &vs_[((ks << 4) + vrow) * QS2 + nj * 16 + vcol]);
                    mma16(o[nj * 2],     pa, vf);
                    mma16(o[nj * 2 + 1], pa, vf + 2);
                }
            }
        }

        if (j + 1 <= jmax) {
            asm volatile("cp.async.wait_group 0;");
            __syncthreads();
        }
    }

    float inv0 = 1.f / l0, inv1 = 1.f / l1;
    size_t orow = (size_t)(b * SS + qbase + pr0) * DD + hoff;
    #pragma unroll
    for (int ni = 0; ni < 8; ni++) {
        int pc = ni * 8 + (tg << 1);
        *(__half2*)&O[orow + pc] =
            __floats2half2_rn(o[ni][0] * inv0, o[ni][1] * inv0);
        *(__half2*)&O[orow + 8 * DD + pc] =
            __floats2half2_rn(o[ni][2] * inv1, o[ni][3] * inv1);
    }
}

// ============================================================================
// launcher
// ============================================================================
#define ATTN_SMEM ((128 + 2 * 64 + 2 * 64) * QS2 * 2)          // 55296 B

extern "C" void kernel_launch(void* const* d_in, const int* in_sizes, int n_in,
                              void* d_out, int out_size)
{
    const float* x  = (const float*)d_in[0];
    const float* Wq = (const float*)d_in[1];
    const float* Wk = (const float*)d_in[2];
    const float* Wv = (const float*)d_in[3];
    const float* Wo = (const float*)d_in[4];
    float* out = (float*)d_out;

    __half *xh, *wqkv, *woh, *qkv, *ah;
    cudaGetSymbolAddress((void**)&xh,   g_xh);
    cudaGetSymbolAddress((void**)&wqkv, g_wqkv);
    cudaGetSymbolAddress((void**)&woh,  g_woh);
    cudaGetSymbolAddress((void**)&qkv,  g_qkv);
    cudaGetSymbolAddress((void**)&ah,   g_ah);

    cudaFuncSetAttribute(gemm_f16<true>,  cudaFuncAttributeMaxDynamicSharedMemorySize, GEMM_SMEM);
    cudaFuncSetAttribute(gemm_f16<false>, cudaFuncAttributeMaxDynamicSharedMemorySize, GEMM_SMEM);
    cudaFuncSetAttribute(attn_kernel,     cudaFuncAttributeMaxDynamicSharedMemorySize, ATTN_SMEM);

    // ONE conversion launch: x + Wq/Wk/Wv (packed) + Wo
    const int NTOT = NX + 4 * NW;                  // 12582912
    convert_all<<<NTOT / 8 / 256, 256>>>(x, Wq, Wk, Wv, Wo, xh, wqkv, woh);

    // fused QKV projection: [8192,1024] x [3072,1024]^T -> [8192,3072] fp16
    dim3 gq(LDQKV / 128, MM / 128);   // (24, 64)
    gemm_f16<true><<<gq, 256, GEMM_SMEM>>>(xh, wqkv, qkv, DD, LDQKV);

    // attention (reads qkv with stride 3072)
    dim3 ga(SS / 128, HH, BB);        // (16, 16, 4)
    attn_kernel<<<ga, 256, ATTN_SMEM>>>(qkv, qkv + DD, qkv + 2 * DD, ah);

    // output projection: [8192,1024] x [1024,1024]^T -> fp32 out
    dim3 go(DD / 128, MM / 128);      // (8, 64)
    gemm_f16<false><<<go, 256, GEMM_SMEM>>>(ah, woh, out, DD, DD);
}

// round 16
// speedup vs baseline: 1.5726x; 1.0287x over previous
#include <cuda_runtime.h>
#include <cuda_fp16.h>
#include <cstdint>

// Problem constants
#define BB   4
#define SS   2048
#define DD   1024
#define HH   16
#define DKK  64
#define MM   (BB*SS)          // 8192 rows
#define LDQKV (3*DD)          // fused qkv row stride
#define NX   (MM*DD)          // 1<<23
#define NW   (DD*DD)          // 1<<20

// -------- scratch (device globals: no allocation allowed) --------
__device__ __half g_xh  [NX];           // x in fp16
__device__ __half g_wqkv[3*NW];         // packed [Wq;Wk;Wv] fp16
__device__ __half g_woh [NW];           // Wo fp16
__device__ __half g_qkv [MM*3*DD];      // fused qkv output
__device__ __half g_ah  [MM*DD];        // attention output

// -------- helpers --------
__device__ __forceinline__ uint32_t s2u(const void* p) {
    return (uint32_t)__cvta_generic_to_shared(p);
}
__device__ __forceinline__ void mma16(float* c, const uint32_t* a, const uint32_t* b) {
    asm volatile(
        "mma.sync.aligned.m16n8k16.row.col.f32.f16.f16.f32 "
        "{%0,%1,%2,%3}, {%4,%5,%6,%7}, {%8,%9}, {%0,%1,%2,%3};"
        : "+f"(c[0]), "+f"(c[1]), "+f"(c[2]), "+f"(c[3])
        : "r"(a[0]), "r"(a[1]), "r"(a[2]), "r"(a[3]), "r"(b[0]), "r"(b[1]));
}
__device__ __forceinline__ void ldsm4(uint32_t* r, const void* p) {
    uint32_t a = s2u(p);
    asm volatile("ldmatrix.sync.aligned.m8n8.x4.shared.b16 {%0,%1,%2,%3}, [%4];"
                 : "=r"(r[0]), "=r"(r[1]), "=r"(r[2]), "=r"(r[3]) : "r"(a));
}
__device__ __forceinline__ void ldsm4t(uint32_t* r, const void* p) {
    uint32_t a = s2u(p);
    asm volatile("ldmatrix.sync.aligned.m8n8.x4.trans.shared.b16 {%0,%1,%2,%3}, [%4];"
                 : "=r"(r[0]), "=r"(r[1]), "=r"(r[2]), "=r"(r[3]) : "r"(a));
}
__device__ __forceinline__ void cp16(void* s, const void* g) {
    uint32_t sa = s2u(s);
    asm volatile("cp.async.cg.shared.global [%0], [%1], 16;" :: "r"(sa), "l"(g));
}
__device__ __forceinline__ uint32_t packh2(float a, float b) {
    __half2 h = __floats2half2_rn(a, b);
    return *(uint32_t*)&h;
}

// ============================================================================
// Fused fp32 -> fp16 conversion of ALL inputs in one launch.
// ============================================================================
__global__ void __launch_bounds__(256) convert_all(
    const float* __restrict__ x,  const float* __restrict__ Wq,
    const float* __restrict__ Wk, const float* __restrict__ Wv,
    const float* __restrict__ Wo,
    __half* __restrict__ xh, __half* __restrict__ wqkv, __half* __restrict__ woh)
{
    int i = (blockIdx.x * blockDim.x + threadIdx.x) << 3;
    const float* src;
    __half* dst;
    int o;
    if (i < NX) {
        src = x; dst = xh; o = i;
    } else {
        int j = i - NX;
        int w = j >> 20;              // which weight (NW = 1<<20)
        o = j & (NW - 1);
        src = (w == 0) ? Wq : (w == 1) ? Wk : (w == 2) ? Wv : Wo;
        dst = (w < 3) ? wqkv + ((size_t)w << 20) : woh;
    }
    float4 v0 = *(const float4*)&src[o];
    float4 v1 = *(const float4*)&src[o + 4];
    uint4 r;
    r.x = packh2(v0.x, v0.y); r.y = packh2(v0.z, v0.w);
    r.z = packh2(v1.x, v1.y); r.w = packh2(v1.z, v1.w);
    *(uint4*)&dst[o] = r;
}

// ============================================================================
// FP16 GEMM: C[M,N] = A[M,K] * B[N,K]^T  (fp32 accum, HMMA)
// CTA tile 128x128, K-tile 64, 3-stage cp.async pipeline, 256 threads
// (8 warps 2x4, warp tile 64x32). 2 CTAs/SM. (At legacy-HMMA ceiling; frozen.)
// ============================================================================
#define GSTR  72                         // smem row stride in halves (144B)
#define AB_ST (128*GSTR)                 // halves per matrix per stage
#define ST_H  (2*AB_ST)
#define NSTG  3
#define GEMM_SMEM (NSTG * ST_H * 2)      // 110592 B -> 2 CTAs/SM

__device__ __forceinline__ void g_stage_load(__half* stg,
    const __half* Ag, const __half* Bg, int K, int kk, int tid)
{
    __half* As = stg;
    __half* Bs = stg + AB_ST;
    #pragma unroll
    for (int i = 0; i < 4; i++) {          // A: 128 rows x 8 chunks
        int idx = tid + (i << 8);
        int r = idx >> 3, c = (idx & 7) << 3;
        cp16(As + r * GSTR + c, Ag + (size_t)r * K + kk + c);
    }
    #pragma unroll
    for (int i = 0; i < 4; i++) {          // B: 128 rows x 8 chunks
        int idx = tid + (i << 8);
        int r = idx >> 3, c = (idx & 7) << 3;
        cp16(Bs + r * GSTR + c, Bg + (size_t)r * K + kk + c);
    }
}

template<bool HALF_OUT>
__global__ void __launch_bounds__(256, 2) gemm_f16(
    const __half* __restrict__ A, const __half* __restrict__ Bw,
    void* __restrict__ Cout, int K, int ldc)
{
    extern __shared__ __half smh[];

    const int tid  = threadIdx.x;
    const int warp = tid >> 5, lane = tid & 31;
    const int wm = (warp >> 2) * 64;      // 0 / 64
    const int wn = (warp & 3) * 32;       // 0..96
    const int g  = lane >> 2, tg = lane & 3;
    const int bn = blockIdx.x * 128, bm = blockIdx.y * 128;

    const int arow = (lane & 7) + ((lane & 8) ? 8 : 0);
    const int acol = (lane & 16) ? 8 : 0;
    const int brow = (lane & 7) + ((lane & 16) ? 8 : 0);
    const int bcol = (lane & 8) ? 8 : 0;

    const __half* Ag = A  + (size_t)bm * K;
    const __half* Bg = Bw + (size_t)bn * K;

    float acc[4][4][4];
    #pragma unroll
    for (int mi = 0; mi < 4; mi++)
        #pragma unroll
        for (int ni = 0; ni < 4; ni++)
            #pragma unroll
            for (int r = 0; r < 4; r++) acc[mi][ni][r] = 0.f;

    const int KT = K >> 6;

    // prologue: stage 0 and 1
    g_stage_load(smh,        Ag, Bg, K, 0,  tid);
    asm volatile("cp.async.commit_group;");
    g_stage_load(smh + ST_H, Ag, Bg, K, 64, tid);
    asm volatile("cp.async.commit_group;");

    int st = 0;
    for (int kt = 0; kt < KT; kt++) {
        if (kt + 1 < KT) asm volatile("cp.async.wait_group 1;");
        else             asm volatile("cp.async.wait_group 0;");
        __syncthreads();

        if (kt + 2 < KT) {
            int ns = st + 2; if (ns >= NSTG) ns -= NSTG;
            g_stage_load(smh + ns * ST_H, Ag, Bg, K, (kt + 2) << 6, tid);
            asm volatile("cp.async.commit_group;");
        }

        const __half* as = smh + st * ST_H;
        const __half* bs = as + AB_ST;

        #pragma unroll
        for (int ks = 0; ks < 4; ks++) {
            const int kk = ks << 4;
            uint32_t af[4][4], bf[2][4];
            #pragma unroll
            for (int mi = 0; mi < 4; mi++)
                ldsm4(af[mi], &as[(wm + mi * 16 + arow) * GSTR + kk + acol]);
            #pragma unroll
            for (int nj = 0; nj < 2; nj++)
                ldsm4(bf[nj], &bs[(wn + nj * 16 + brow) * GSTR + kk + bcol]);
            #pragma unroll
            for (int mi = 0; mi < 4; mi++)
                #pragma unroll
                for (int nj = 0; nj < 2; nj++) {
                    mma16(acc[mi][nj * 2],     af[mi], bf[nj]);
                    mma16(acc[mi][nj * 2 + 1], af[mi], bf[nj] + 2);
                }
        }

        if (++st >= NSTG) st = 0;
    }

    // epilogue
    #pragma unroll
    for (int mi = 0; mi < 4; mi++) {
        int row = bm + wm + mi * 16 + g;
        #pragma unroll
        for (int ni = 0; ni < 4; ni++) {
            int col = bn + wn + ni * 8 + (tg << 1);
            if (HALF_OUT) {
                __half* C = (__half*)Cout;
                *(__half2*)&C[(size_t)row * ldc + col] =
                    __floats2half2_rn(acc[mi][ni][0], acc[mi][ni][1]);
                *(__half2*)&C[(size_t)(row + 8) * ldc + col] =
                    __floats2half2_rn(acc[mi][ni][2], acc[mi][ni][3]);
            } else {
                float* C = (float*)Cout;
                *(float2*)&C[(size_t)row * ldc + col] =
                    make_float2(acc[mi][ni][0], acc[mi][ni][1]);
                *(float2*)&C[(size_t)(row + 8) * ldc + col] =
                    make_float2(acc[mi][ni][2], acc[mi][ni][3]);
            }
        }
    }
}

// ============================================================================
// Causal flash attention. Softmax in log2 domain with packed h2exp2; the
// exp2 results are aliased back into sc[] (dead at that point) so peak regs
// fit the 128-reg cap, and __launch_bounds__(256, 2) forces 2 CTAs/SM.
// ============================================================================
#define QS2 72   // smem row stride in halves

__global__ void __launch_bounds__(256, 2) attn_kernel(
    const __half* __restrict__ Q, const __half* __restrict__ Kb,
    const __half* __restrict__ Vb, __half* __restrict__ O)
{
    extern __shared__ __half sm[];
    __half* Qs = sm;                       // 128 x QS2
    __half* Ks = Qs + 128 * QS2;           // [2][64][QS2]
    __half* Vs = Ks + 2 * 64 * QS2;        // [2][64][QS2]

    const int tid  = threadIdx.x;
    const int warp = tid >> 5, lane = tid & 31;
    const int g = lane >> 2, tg = lane & 3;
    const int qtile = (gridDim.x - 1) - blockIdx.x;   // longest first
    const int h = blockIdx.y, b = blockIdx.z;
    const int qbase = qtile * 128;
    const int hoff  = h * DKK;

    const int arow = (lane & 7) + ((lane & 8) ? 8 : 0);
    const int acol = (lane & 16) ? 8 : 0;
    const int brow = (lane & 7) + ((lane & 16) ? 8 : 0);
    const int bcol = (lane & 8) ? 8 : 0;
    const int vrow = (lane & 7) + ((lane & 8) ? 8 : 0);
    const int vcol = (lane & 16) ? 8 : 0;

    #pragma unroll
    for (int i = 0; i < 4; i++) {
        int idx = tid + (i << 8);
        int r = idx >> 3, c = (idx & 7) << 3;
        cp16(Qs + r * QS2 + c, Q + (size_t)(b * SS + qbase + r) * LDQKV + hoff + c);
    }
    #pragma unroll
    for (int i = 0; i < 4; i++) {
        int idx = tid + (i << 8);
        int mat = idx >> 9, r = (idx >> 3) & 63, c = (idx & 7) << 3;
        const __half* src = Kb;
        __half* dst = Ks;
        if (mat) { src = Vb; dst = Vs; }
        cp16(dst + r * QS2 + c, src + (size_t)(b * SS + r) * LDQKV + hoff + c);
    }
    asm volatile("cp.async.commit_group;");
    asm volatile("cp.async.wait_group 0;");
    __syncthreads();

    uint32_t qf[4][4];
    #pragma unroll
    for (int ks = 0; ks < 4; ks++)
        ldsm4(qf[ks], &Qs[(warp * 16 + arow) * QS2 + (ks << 4) + acol]);

    float m0 = -1e30f, m1 = -1e30f, l0 = 0.f, l1 = 0.f;
    float o[8][4];
    #pragma unroll
    for (int ni = 0; ni < 8; ni++)
        #pragma unroll
        for (int r = 0; r < 4; r++) o[ni][r] = 0.f;

    const int pr0 = warp * 16 + g;
    const int r0g = qbase + pr0;
    const int r1g = r0g + 8;
    const float qscale = 0.125f * 1.44269504089f;  // 1/sqrt(64) * log2(e)
    const int jmax = (qbase + 127) >> 6;

    for (int j = 0; j <= jmax; j++) {
        const int kvbase = j << 6;
        const int cur = j & 1;

        if (j + 1 <= jmax) {
            const int nb = (j + 1) & 1;
            const int nkv = (j + 1) << 6;
            #pragma unroll
            for (int i = 0; i < 4; i++) {
                int idx = tid + (i << 8);
                int mat = idx >> 9, r = (idx >> 3) & 63, c = (idx & 7) << 3;
                const __half* src = Kb;
                __half* dst = Ks + nb * 64 * QS2;
                if (mat) { src = Vb; dst = Vs + nb * 64 * QS2; }
                cp16(dst + r * QS2 + c, src + (size_t)(b * SS + nkv + r) * LDQKV + hoff + c);
            }
            asm volatile("cp.async.commit_group;");
        }

        if (kvbase <= qbase + warp * 16 + 15) {
            const __half* ks_ = Ks + cur * 64 * QS2;
            const __half* vs_ = Vs + cur * 64 * QS2;

            float sc[8][4];
            #pragma unroll
            for (int ni = 0; ni < 8; ni++)
                #pragma unroll
                for (int r = 0; r < 4; r++) sc[ni][r] = 0.f;

            #pragma unroll
            for (int ks = 0; ks < 4; ks++) {
                const int kk = ks << 4;
                #pragma unroll
                for (int nj = 0; nj < 4; nj++) {
                    uint32_t kf[4];
                    ldsm4(kf, &ks_[(nj * 16 + brow) * QS2 + kk + bcol]);
                    mma16(sc[nj * 2],     qf[ks], kf);
                    mma16(sc[nj * 2 + 1], qf[ks], kf + 2);
                }
            }

            // ---- scale into log2 domain + causal mask ----
            const bool need_mask = (kvbase + 63 > qbase + warp * 16);
            if (need_mask) {
                #pragma unroll
                for (int ni = 0; ni < 8; ni++) {
                    int c0 = kvbase + ni * 8 + (tg << 1), c1 = c0 + 1;
                    sc[ni][0] = (c0 <= r0g) ? sc[ni][0] * qscale : -1e30f;
                    sc[ni][1] = (c1 <= r0g) ? sc[ni][1] * qscale : -1e30f;
                    sc[ni][2] = (c0 <= r1g) ? sc[ni][2] * qscale : -1e30f;
                    sc[ni][3] = (c1 <= r1g) ? sc[ni][3] * qscale : -1e30f;
                }
            } else {
                #pragma unroll
                for (int ni = 0; ni < 8; ni++)
                    #pragma unroll
                    for (int r = 0; r < 4; r++) sc[ni][r] *= qscale;
            }

            // ---- online softmax (log2 domain, quad shuffles) ----
            float t0 = -1e30f, t1 = -1e30f;
            #pragma unroll
            for (int ni = 0; ni < 8; ni++) {
                t0 = fmaxf(t0, fmaxf(sc[ni][0], sc[ni][1]));
                t1 = fmaxf(t1, fmaxf(sc[ni][2], sc[ni][3]));
            }
            t0 = fmaxf(t0, __shfl_xor_sync(0xffffffffu, t0, 1));
            t0 = fmaxf(t0, __shfl_xor_sync(0xffffffffu, t0, 2));
            t1 = fmaxf(t1, __shfl_xor_sync(0xffffffffu, t1, 1));
            t1 = fmaxf(t1, __shfl_xor_sync(0xffffffffu, t1, 2));

            float nm0 = fmaxf(m0, t0), nm1 = fmaxf(m1, t1);
            float cor0 = exp2f(m0 - nm0), cor1 = exp2f(m1 - nm1);

            // p = exp2(s' - m') packed; result aliased back into sc[ni][0..1]
            float s0 = 0.f, s1 = 0.f;
            #pragma unroll
            for (int ni = 0; ni < 8; ni++) {
                __half2 h0 = __floats2half2_rn(sc[ni][0] - nm0, sc[ni][1] - nm0);
                __half2 h1 = __floats2half2_rn(sc[ni][2] - nm1, sc[ni][3] - nm1);
                __half2 e0 = h2exp2(h0);
                __half2 e1 = h2exp2(h1);
                float2 f0 = __half22float2(e0);
                float2 f1 = __half22float2(e1);
                s0 += f0.x + f0.y;
                s1 += f1.x + f1.y;
                sc[ni][0] = __uint_as_float(*(uint32_t*)&e0);   // pe row0 pair
                sc[ni][1] = __uint_as_float(*(uint32_t*)&e1);   // pe row1 pair
            }
            s0 += __shfl_xor_sync(0xffffffffu, s0, 1);
            s0 += __shfl_xor_sync(0xffffffffu, s0, 2);
            s1 += __shfl_xor_sync(0xffffffffu, s1, 1);
            s1 += __shfl_xor_sync(0xffffffffu, s1, 2);

            l0 = l0 * cor0 + s0;
            l1 = l1 * cor1 + s1;
            m0 = nm0; m1 = nm1;

            #pragma unroll
            for (int ni = 0; ni < 8; ni++) {
                o[ni][0] *= cor0; o[ni][1] *= cor0;
                o[ni][2] *= cor1; o[ni][3] *= cor1;
            }

            // ---- O += P V ----
            #pragma unroll
            for (int ks = 0; ks < 4; ks++) {
                uint32_t pa[4];
                pa[0] = __float_as_uint(sc[2 * ks][0]);
                pa[1] = __float_as_uint(sc[2 * ks][1]);
                pa[2] = __float_as_uint(sc[2 * ks + 1][0]);
                pa[3] = __float_as_uint(sc[2 * ks + 1][1]);
                #pragma unroll
                for (int nj = 0; nj < 4; nj++) {
                    uint32_t vf[4];
                    ldsm4t(vf, &vs_[((ks << 4) + vrow) * QS2 + nj * 16 + vcol]);
                    mma16(o[nj * 2],     pa, vf);
                    mma16(o[nj * 2 + 1], pa, vf + 2);
                }
            }
        }

        if (j + 1 <= jmax) {
            asm volatile("cp.async.wait_group 0;");
            __syncthreads();
        }
    }

    float inv0 = 1.f / l0, inv1 = 1.f / l1;
    size_t orow = (size_t)(b * SS + qbase + pr0) * DD + hoff;
    #pragma unroll
    for (int ni = 0; ni < 8; ni++) {
        int pc = ni * 8 + (tg << 1);
        *(__half2*)&O[orow + pc] =
            __floats2half2_rn(o[ni][0] * inv0, o[ni][1] * inv0);
        *(__half2*)&O[orow + 8 * DD + pc] =
            __floats2half2_rn(o[ni][2] * inv1, o[ni][3] * inv1);
    }
}

// ============================================================================
// launcher
// ============================================================================
#define ATTN_SMEM ((128 + 2 * 64 + 2 * 64) * QS2 * 2)          // 55296 B

extern "C" void kernel_launch(void* const* d_in, const int* in_sizes, int n_in,
                              void* d_out, int out_size)
{
    const float* x  = (const float*)d_in[0];
    const float* Wq = (const float*)d_in[1];
    const float* Wk = (const float*)d_in[2];
    const float* Wv = (const float*)d_in[3];
    const float* Wo = (const float*)d_in[4];
    float* out = (float*)d_out;

    __half *xh, *wqkv, *woh, *qkv, *ah;
    cudaGetSymbolAddress((void**)&xh,   g_xh);
    cudaGetSymbolAddress((void**)&wqkv, g_wqkv);
    cudaGetSymbolAddress((void**)&woh,  g_woh);
    cudaGetSymbolAddress((void**)&qkv,  g_qkv);
    cudaGetSymbolAddress((void**)&ah,   g_ah);

    cudaFuncSetAttribute(gemm_f16<true>,  cudaFuncAttributeMaxDynamicSharedMemorySize, GEMM_SMEM);
    cudaFuncSetAttribute(gemm_f16<false>, cudaFuncAttributeMaxDynamicSharedMemorySize, GEMM_SMEM);
    cudaFuncSetAttribute(attn_kernel,     cudaFuncAttributeMaxDynamicSharedMemorySize, ATTN_SMEM);

    // ONE conversion launch: x + Wq/Wk/Wv (packed) + Wo
    const int NTOT = NX + 4 * NW;                  // 12582912
    convert_all<<<NTOT / 8 / 256, 256>>>(x, Wq, Wk, Wv, Wo, xh, wqkv, woh);

    // fused QKV projection: [8192,1024] x [3072,1024]^T -> [8192,3072] fp16
    dim3 gq(LDQKV / 128, MM / 128);   // (24, 64)
    gemm_f16<true><<<gq, 256, GEMM_SMEM>>>(xh, wqkv, qkv, DD, LDQKV);

    // attention (reads qkv with stride 3072)
    dim3 ga(SS / 128, HH, BB);        // (16, 16, 4)
    attn_kernel<<<ga, 256, ATTN_SMEM>>>(qkv, qkv + DD, qkv + 2 * DD, ah);

    // output projection: [8192,1024] x [1024,1024]^T -> fp32 out
    dim3 go(DD / 128, MM / 128);      // (8, 64)
    gemm_f16<false><<<go, 256, GEMM_SMEM>>>(ah, woh, out, DD, DD);
}